// round 2
// baseline (speedup 1.0000x reference)
#include <cuda_runtime.h>
#include <math.h>

#define NT 256
#define ROWS 16
#define L 336
#define OFF_MU (1024*96*7)
#define OFF_LV (OFF_MU + 7168*64)
#define OFF_LD (OFF_LV + 7168*64)
#define SMEM_FLOATS 19280
#define SMEM_BYTES (SMEM_FLOATS*4)

__device__ float g_Wsc[128*336];
__device__ float g_Wr3[128*512];
__device__ float g_Wml[128*128];
__device__ float g_bml[128];
__device__ float g_Wc[128*16];
__device__ float g_bc[128];
__device__ double g_uhat[8*64];
__device__ double g_cflow[8];

__global__ void prep_kernel(const float* __restrict__ W_sc,
                            const float* __restrict__ W_mu, const float* __restrict__ b_mu,
                            const float* __restrict__ W_lv, const float* __restrict__ b_lv,
                            const float* __restrict__ W_r3,
                            const float* __restrict__ W_fu, const float* __restrict__ b_fu,
                            const float* __restrict__ W_ts, const float* __restrict__ b_ts,
                            const float* __restrict__ flow_u, const float* __restrict__ flow_w)
{
    int idx = blockIdx.x * blockDim.x + threadIdx.x;
    int stride = gridDim.x * blockDim.x;
    const int E0 = 128*336;
    const int E1 = E0 + 128*512;
    const int E2 = E1 + 128*128;
    const int E3 = E2 + 128;
    const int E4 = E3 + 128*16;
    const int E5 = E4 + 128;
    const int E6 = E5 + 8;
    for (int i = idx; i < E6; i += stride) {
        if (i < E0) {
            g_Wsc[i] = (i < 96*336) ? W_sc[i] : 0.f;
        } else if (i < E1) {
            int j = i - E0;
            g_Wr3[j] = (j < 96*512) ? W_r3[j] : 0.f;
        } else if (i < E2) {
            int j = i - E1;
            int m = j >> 7, k = j & 127;
            g_Wml[j] = (m < 64) ? W_mu[m*128 + k] : W_lv[(m-64)*128 + k];
        } else if (i < E3) {
            int j = i - E2;
            g_bml[j] = (j < 64) ? b_mu[j] : b_lv[j-64];
        } else if (i < E4) {
            int j = i - E3;
            int h = j >> 4, l = j & 15;
            float s = 0.f;
            for (int d = 0; d < 128; d++) s += W_fu[h*256 + d] * W_ts[d*16 + l];
            g_Wc[j] = s;
        } else if (i < E5) {
            int h = i - E4;
            float s = 0.f;
            for (int d = 0; d < 128; d++) s += W_fu[h*256 + d] * b_ts[d];
            g_bc[h] = s + b_fu[h];
        } else {
            int fi = i - E5;
            double s = 0.0, wsq = 0.0;
            for (int d = 0; d < 64; d++) {
                double u = (double)flow_u[fi*64+d], w = (double)flow_w[fi*64+d];
                s += u*w; wsq += w*w;
            }
            double sp = (s > 0.0) ? s + log1p(exp(-s)) : log1p(exp(s));
            double m = -1.0 + sp;
            double coef = m / (wsq + 1e-6);
            for (int d = 0; d < 64; d++)
                g_uhat[fi*64+d] = (double)flow_u[fi*64+d] + coef*(double)flow_w[fi*64+d];
            g_cflow[fi] = s + coef * wsq;
        }
    }
}

__device__ __forceinline__ float gelu_f(float x) {
    return 0.5f * x * (1.f + erff(x * 0.70710678118654752f));
}

// Block-cooperative GEMM: OUT[16 x M] = IN[16 x K] @ W[M x K]^T + bias, optional GELU.
// Weights staged in smem transposed tiles Wt[16][130] (conflict-free float2 reads).
// Thread microtile: 4 rows x 2 outputs. Requires K % 16 == 0, M even.
__device__ void gemm_tile(const float* smIn, int pitch, int K,
                          const float* __restrict__ Wg, const float* __restrict__ bias,
                          int M, float* smOut, int opitch, int act, float* Wt)
{
    int tid = threadIdx.x;
    int rg = tid >> 6;             // 0..3 -> rows rg*4 .. rg*4+3
    int mloc = (tid & 63) << 1;    // 0..126 even
    const float* in0 = smIn + (rg*4 + 0)*pitch;
    const float* in1 = in0 + pitch;
    const float* in2 = in1 + pitch;
    const float* in3 = in2 + pitch;
    for (int m0 = 0; m0 < M; m0 += 128) {
        float a00=0.f,a01=0.f,a10=0.f,a11=0.f,a20=0.f,a21=0.f,a30=0.f,a31=0.f;
        for (int k0 = 0; k0 < K; k0 += 16) {
            __syncthreads();
            {
                const float* src = Wg + (size_t)m0*K + k0;
                #pragma unroll
                for (int j = tid; j < 2048; j += NT) {
                    int mm = j >> 4, kk = j & 15;
                    Wt[kk*130 + mm] = src[(size_t)mm*K + kk];
                }
            }
            __syncthreads();
            #pragma unroll
            for (int kk = 0; kk < 16; kk += 2) {
                float2 w0 = *(const float2*)&Wt[kk*130 + mloc];
                float2 w1 = *(const float2*)&Wt[(kk+1)*130 + mloc];
                float2 x0 = *(const float2*)(in0 + k0 + kk);
                float2 x1 = *(const float2*)(in1 + k0 + kk);
                float2 x2 = *(const float2*)(in2 + k0 + kk);
                float2 x3 = *(const float2*)(in3 + k0 + kk);
                a00 = fmaf(x0.x, w0.x, a00); a00 = fmaf(x0.y, w1.x, a00);
                a01 = fmaf(x0.x, w0.y, a01); a01 = fmaf(x0.y, w1.y, a01);
                a10 = fmaf(x1.x, w0.x, a10); a10 = fmaf(x1.y, w1.x, a10);
                a11 = fmaf(x1.x, w0.y, a11); a11 = fmaf(x1.y, w1.y, a11);
                a20 = fmaf(x2.x, w0.x, a20); a20 = fmaf(x2.y, w1.x, a20);
                a21 = fmaf(x2.x, w0.y, a21); a21 = fmaf(x2.y, w1.y, a21);
                a30 = fmaf(x3.x, w0.x, a30); a30 = fmaf(x3.y, w1.x, a30);
                a31 = fmaf(x3.x, w0.y, a31); a31 = fmaf(x3.y, w1.y, a31);
            }
        }
        int m = m0 + mloc;
        if (m < M) {
            float b0 = bias[m], b1 = bias[m+1];
            int r0 = rg*4;
            float v;
            v = a00 + b0; if (act) v = gelu_f(v); smOut[(r0+0)*opitch + m]   = v;
            v = a01 + b1; if (act) v = gelu_f(v); smOut[(r0+0)*opitch + m+1] = v;
            v = a10 + b0; if (act) v = gelu_f(v); smOut[(r0+1)*opitch + m]   = v;
            v = a11 + b1; if (act) v = gelu_f(v); smOut[(r0+1)*opitch + m+1] = v;
            v = a20 + b0; if (act) v = gelu_f(v); smOut[(r0+2)*opitch + m]   = v;
            v = a21 + b1; if (act) v = gelu_f(v); smOut[(r0+2)*opitch + m+1] = v;
            v = a30 + b0; if (act) v = gelu_f(v); smOut[(r0+3)*opitch + m]   = v;
            v = a31 + b1; if (act) v = gelu_f(v); smOut[(r0+3)*opitch + m+1] = v;
        }
    }
}

__global__ void __launch_bounds__(NT, 3) fused_kernel(
    const float* __restrict__ x_enc, const float* __restrict__ eps,
    const float* __restrict__ p_aw, const float* __restrict__ p_ab,
    const float* __restrict__ b_sc,
    const float* __restrict__ W_r1, const float* __restrict__ b_r1,
    const float* __restrict__ W_r2, const float* __restrict__ b_r2,
    const float* __restrict__ b_r3,
    const float* __restrict__ flow_w, const float* __restrict__ flow_b,
    float* __restrict__ out)
{
    extern __shared__ float smn[];
    float* sA    = smn;             // 8192 floats: xn[16][336] then r2[16][512]
    float* sSC   = sA + 8192;       // 1536: shortcut[16][96]
    float* sINP  = sSC + 1536;      // 3072: inp[16][192] = [z | h]
    float* sB    = sINP + 3072;     // 4096: ml[16][128] / r1[16][256] / recon[16][96]
    float* sPB   = sB + 4096;       // 256: pbar[16][16]
    float* sWT   = sPB + 256;       // 2080: weight tile [16][130]
    float* sMean = sWT + 2080;      // 16
    float* sStd  = sMean + 16;      // 16
    float* sScale= sStd + 16;       // 16

    int tid = threadIdx.x;
    int n0 = blockIdx.x * ROWS;
    float aw = p_aw[0], ab = p_ab[0];
    int warp = tid >> 5, lane = tid & 31;

    // ---- 1. load x (x_enc[b][l][c] -> xn_raw[r][l], n = b*7+c) ----
    for (int t = tid; t < ROWS*L; t += NT) {
        int r = t & 15, l = t >> 4;
        int n = n0 + r;
        int b = n / 7, c = n - b*7;
        sA[r*L + l] = x_enc[(b*L + l)*7 + c];
    }
    __syncthreads();

    // ---- 2. per-row mean/std (warp w handles rows 2w, 2w+1) ----
    #pragma unroll
    for (int rr = 0; rr < 2; rr++) {
        int r = warp*2 + rr;
        const float* row = sA + r*L;
        float s = 0.f, sq = 0.f;
        for (int l2 = lane; l2 < L; l2 += 32) { float v = row[l2]; s += v; sq += v*v; }
        #pragma unroll
        for (int o = 16; o > 0; o >>= 1) {
            s  += __shfl_xor_sync(0xffffffffu, s, o);
            sq += __shfl_xor_sync(0xffffffffu, sq, o);
        }
        if (lane == 0) {
            float mean = s * (1.f/336.f);
            float var = sq * (1.f/336.f) - mean*mean;
            float sd = sqrtf(var + 1e-5f);
            sMean[r] = mean; sStd[r] = sd; sScale[r] = aw / sd;
        }
    }
    __syncthreads();

    // ---- 3. normalize in place ----
    for (int t = tid; t < ROWS*L; t += NT) {
        int r = t / L;
        smn[t] = (smn[t] - sMean[r]) * sScale[r] + ab;   // sA == smn base
    }
    __syncthreads();

    // ---- 4. pbar[r][j] = mean over 41 patches of xn[r][8p+j] ----
    {
        int r = tid >> 4, j = tid & 15;
        float s = 0.f;
        #pragma unroll
        for (int pp = 0; pp < 41; pp++) s += sA[r*L + pp*8 + j];
        sPB[r*16 + j] = s * (1.f/41.f);
    }
    __syncthreads();

    // ---- 5. shortcut = xn @ Wsc^T + b_sc ----
    gemm_tile(sA, L, L, g_Wsc, b_sc, 96, sSC, 96, 0, sWT);
    // ---- 6. h = pbar @ Wc^T + bc  -> inp[:,64:192] ----
    gemm_tile(sPB, 16, 16, g_Wc, g_bc, 128, sINP + 64, 192, 0, sWT);
    __syncthreads();
    // ---- 7. [mu|lv] = h @ Wml^T + bml ----
    gemm_tile(sINP + 64, 192, 128, g_Wml, g_bml, 128, sB, 128, 0, sWT);
    __syncthreads();

    // ---- 8+9. reparam (FP64) + planar flows (FP64 scalar chain).
    // Warp per row: rows warp and warp+8. Lane handles dims lane and 32+lane.
    #pragma unroll
    for (int rr = 0; rr < 2; rr++) {
        int r = warp + rr*8;
        int n = n0 + r;
        float mu0 = sB[r*128 + lane];
        float mu1 = sB[r*128 + 32 + lane];
        float lv0 = sB[r*128 + 64 + lane];
        float lv1 = sB[r*128 + 96 + lane];
        out[OFF_MU + n*64 + lane]      = mu0;
        out[OFF_MU + n*64 + 32 + lane] = mu1;
        out[OFF_LV + n*64 + lane]      = lv0;
        out[OFF_LV + n*64 + 32 + lane] = lv1;
        double z0 = (double)mu0 + (double)eps[n*64 + lane]      * exp(0.5 * (double)lv0);
        double z1 = (double)mu1 + (double)eps[n*64 + 32 + lane] * exp(0.5 * (double)lv1);
        double ld = 0.0;
        #pragma unroll
        for (int i = 0; i < 8; i++) {
            double w0 = (double)flow_w[i*64 + lane];
            double w1 = (double)flow_w[i*64 + 32 + lane];
            double dot = z0*w0 + z1*w1;
            #pragma unroll
            for (int o = 16; o > 0; o >>= 1) dot += __shfl_xor_sync(0xffffffffu, dot, o);
            double th = tanh(dot + (double)flow_b[i]);
            z0 += th * g_uhat[i*64 + lane];
            z1 += th * g_uhat[i*64 + 32 + lane];
            ld += log(fabs(1.0 + (1.0 - th*th) * g_cflow[i]) + 1e-6);
        }
        sINP[r*192 + lane]      = (float)z0;
        sINP[r*192 + 32 + lane] = (float)z1;
        if (lane == 0) out[OFF_LD + n] = (float)ld;
    }
    __syncthreads();

    // ---- 10-12. decoder ----
    gemm_tile(sINP, 192, 192, W_r1, b_r1, 256, sB, 256, 1, sWT);   // r1 (gelu)
    __syncthreads();
    gemm_tile(sB, 256, 256, W_r2, b_r2, 512, sA, 512, 1, sWT);     // r2 (gelu), reuses xn space
    __syncthreads();
    gemm_tile(sA, 512, 512, g_Wr3, b_r3, 96, sB, 96, 0, sWT);      // recon
    __syncthreads();

    // ---- 13. denorm + scatter out[b][p][c] ----
    float inv_aw = 1.f / (aw + 1e-10f);
    for (int t = tid; t < ROWS*96; t += NT) {
        int r = t & 15, pcol = t >> 4;
        int n = n0 + r;
        float v = sB[r*96 + pcol] + sSC[r*96 + pcol];
        float den = fmaf((v - ab) * inv_aw, sStd[r], sMean[r]);
        int b = n/7, c = n - b*7;
        out[(b*96 + pcol)*7 + c] = den;
    }
}

extern "C" void kernel_launch(void* const* d_in, const int* in_sizes, int n_in,
                              void* d_out, int out_size) {
    const float* x_enc  = (const float*)d_in[0];
    const float* eps    = (const float*)d_in[1];
    const float* aw     = (const float*)d_in[2];
    const float* ab     = (const float*)d_in[3];
    const float* W_sc   = (const float*)d_in[4];
    const float* b_sc   = (const float*)d_in[5];
    const float* W_ts   = (const float*)d_in[6];
    const float* b_ts   = (const float*)d_in[7];
    const float* W_fu   = (const float*)d_in[8];
    const float* b_fu   = (const float*)d_in[9];
    const float* W_mu   = (const float*)d_in[10];
    const float* b_mu   = (const float*)d_in[11];
    const float* W_lv   = (const float*)d_in[12];
    const float* b_lv   = (const float*)d_in[13];
    const float* flow_u = (const float*)d_in[14];
    const float* flow_w = (const float*)d_in[15];
    const float* flow_b = (const float*)d_in[16];
    const float* W_r1   = (const float*)d_in[17];
    const float* b_r1   = (const float*)d_in[18];
    const float* W_r2   = (const float*)d_in[19];
    const float* b_r2   = (const float*)d_in[20];
    const float* W_r3   = (const float*)d_in[21];
    const float* b_r3   = (const float*)d_in[22];
    float* out = (float*)d_out;

    cudaFuncSetAttribute(fused_kernel, cudaFuncAttributeMaxDynamicSharedMemorySize, SMEM_BYTES);

    prep_kernel<<<128, 256>>>(W_sc, W_mu, b_mu, W_lv, b_lv, W_r3,
                              W_fu, b_fu, W_ts, b_ts, flow_u, flow_w);
    fused_kernel<<<448, NT, SMEM_BYTES>>>(x_enc, eps, aw, ab, b_sc,
                                          W_r1, b_r1, W_r2, b_r2, b_r3,
                                          flow_w, flow_b, out);
}

// round 3
// speedup vs baseline: 1.3810x; 1.3810x over previous
#include <cuda_runtime.h>
#include <math.h>

#define NT 256
#define ROWS 16
#define L 336
#define OFF_MU (1024*96*7)
#define OFF_LV (OFF_MU + 7168*64)
#define OFF_LD (OFF_LV + 7168*64)

// smem pool layout (floats)
#define P_XN    0        // xn[16][336] (pitch 336); later r2[16][512] (pitch 512) at 0..8192
#define P_INP   5376     // inp[16][192] = [z | h]   5376..8448
#define P_B     8448     // ml[16][128] / r1[16][256] / recon[16][96]  8448..12544
#define P_PB    12544    // pbar[16][16]             12544..12800
#define P_WT    12800    // weight tiles 2 x [16][130] = 4160   12800..16960
#define P_MEAN  16960
#define P_STD   16976
#define P_SCALE 16992
#define SMEM_FLOATS 17008
#define SMEM_BYTES (SMEM_FLOATS*4)

__device__ float g_Wsc[128*336];
__device__ float g_Wr3[128*512];
__device__ float g_Wml[128*128];
__device__ float g_bml[128];
__device__ float g_Wc[128*16];
__device__ float g_bc[128];
__device__ double g_uhat[8*64];
__device__ double g_cflow[8];
__device__ float g_short[7168*96];   // shortcut scratch (gmem)

__global__ void prep_kernel(const float* __restrict__ W_sc,
                            const float* __restrict__ W_mu, const float* __restrict__ b_mu,
                            const float* __restrict__ W_lv, const float* __restrict__ b_lv,
                            const float* __restrict__ W_r3,
                            const float* __restrict__ W_fu, const float* __restrict__ b_fu,
                            const float* __restrict__ W_ts, const float* __restrict__ b_ts,
                            const float* __restrict__ flow_u, const float* __restrict__ flow_w)
{
    int idx = blockIdx.x * blockDim.x + threadIdx.x;
    int stride = gridDim.x * blockDim.x;
    const int E0 = 128*336;
    const int E1 = E0 + 128*512;
    const int E2 = E1 + 128*128;
    const int E3 = E2 + 128;
    const int E4 = E3 + 128*16;
    const int E5 = E4 + 128;
    const int E6 = E5 + 8;
    for (int i = idx; i < E6; i += stride) {
        if (i < E0) {
            g_Wsc[i] = (i < 96*336) ? W_sc[i] : 0.f;
        } else if (i < E1) {
            int j = i - E0;
            g_Wr3[j] = (j < 96*512) ? W_r3[j] : 0.f;
        } else if (i < E2) {
            int j = i - E1;
            int m = j >> 7, k = j & 127;
            g_Wml[j] = (m < 64) ? W_mu[m*128 + k] : W_lv[(m-64)*128 + k];
        } else if (i < E3) {
            int j = i - E2;
            g_bml[j] = (j < 64) ? b_mu[j] : b_lv[j-64];
        } else if (i < E4) {
            int j = i - E3;
            int h = j >> 4, l = j & 15;
            float s = 0.f;
            for (int d = 0; d < 128; d++) s += W_fu[h*256 + d] * W_ts[d*16 + l];
            g_Wc[j] = s;
        } else if (i < E5) {
            int h = i - E4;
            float s = 0.f;
            for (int d = 0; d < 128; d++) s += W_fu[h*256 + d] * b_ts[d];
            g_bc[h] = s + b_fu[h];
        } else {
            int fi = i - E5;
            double s = 0.0, wsq = 0.0;
            for (int d = 0; d < 64; d++) {
                double u = (double)flow_u[fi*64+d], w = (double)flow_w[fi*64+d];
                s += u*w; wsq += w*w;
            }
            double sp = (s > 0.0) ? s + log1p(exp(-s)) : log1p(exp(s));
            double m = -1.0 + sp;
            double coef = m / (wsq + 1e-6);
            for (int d = 0; d < 64; d++)
                g_uhat[fi*64+d] = (double)flow_u[fi*64+d] + coef*(double)flow_w[fi*64+d];
            g_cflow[fi] = s + coef * wsq;
        }
    }
}

__device__ __forceinline__ float gelu_f(float x) {
    return 0.5f * x * (1.f + erff(x * 0.70710678118654752f));
}

// Block-cooperative GEMM: OUT[16 x M] = IN[16 x K] @ W[M x K]^T + bias, optional GELU.
// Double-buffered smem weight tiles (2 x [16][130]) with register prefetch:
// LDG for tile t+2 overlaps compute of tile t; one barrier per k-tile.
// Thread microtile: 4 rows x 2 outputs. K % 16 == 0. W must have >= ceil(M,128) rows.
__device__ __forceinline__ void gemm_tile(const float* smIn, int pitch, int K,
                          const float* __restrict__ Wg, const float* __restrict__ bias,
                          int M, float* smOut, int opitch, int act, float* Wt)
{
    int tid = threadIdx.x;
    int rg = tid >> 6;             // 0..3 -> rows rg*4 .. rg*4+3
    int mloc = (tid & 63) << 1;    // 0..126 even
    int kk_st = tid & 15;          // this thread stages column kk_st of tiles
    int mm0 = tid >> 4;            // and rows mm0 + 16*s
    const float* in0 = smIn + (rg*4 + 0)*pitch;
    const float* in1 = in0 + pitch;
    const float* in2 = in1 + pitch;
    const float* in3 = in2 + pitch;
    int T = K >> 4;
    for (int m0 = 0; m0 < M; m0 += 128) {
        const float* Wsrc = Wg + (size_t)m0*K + kk_st;
        float r[8];
        #pragma unroll
        for (int s = 0; s < 8; s++) r[s] = Wsrc[(size_t)(mm0 + 16*s)*K];
        __syncthreads();                       // prior users of Wt done
        #pragma unroll
        for (int s = 0; s < 8; s++) Wt[kk_st*130 + mm0 + 16*s] = r[s];
        if (T > 1) {
            #pragma unroll
            for (int s = 0; s < 8; s++) r[s] = Wsrc[(size_t)(mm0 + 16*s)*K + 16];
        }
        __syncthreads();                       // tile 0 ready
        float a00=0.f,a01=0.f,a10=0.f,a11=0.f,a20=0.f,a21=0.f,a30=0.f,a31=0.f;
        int buf = 0;
        for (int t = 0; t < T; t++) {
            const float* W = Wt + buf*2080;
            const float* i0 = in0 + t*16;
            const float* i1 = in1 + t*16;
            const float* i2 = in2 + t*16;
            const float* i3 = in3 + t*16;
            #pragma unroll
            for (int kk = 0; kk < 16; kk += 2) {
                float2 w0 = *(const float2*)&W[kk*130 + mloc];
                float2 w1 = *(const float2*)&W[(kk+1)*130 + mloc];
                float2 x0 = *(const float2*)(i0 + kk);
                float2 x1 = *(const float2*)(i1 + kk);
                float2 x2 = *(const float2*)(i2 + kk);
                float2 x3 = *(const float2*)(i3 + kk);
                a00 = fmaf(x0.x, w0.x, a00); a00 = fmaf(x0.y, w1.x, a00);
                a01 = fmaf(x0.x, w0.y, a01); a01 = fmaf(x0.y, w1.y, a01);
                a10 = fmaf(x1.x, w0.x, a10); a10 = fmaf(x1.y, w1.x, a10);
                a11 = fmaf(x1.x, w0.y, a11); a11 = fmaf(x1.y, w1.y, a11);
                a20 = fmaf(x2.x, w0.x, a20); a20 = fmaf(x2.y, w1.x, a20);
                a21 = fmaf(x2.x, w0.y, a21); a21 = fmaf(x2.y, w1.y, a21);
                a30 = fmaf(x3.x, w0.x, a30); a30 = fmaf(x3.y, w1.x, a30);
                a31 = fmaf(x3.x, w0.y, a31); a31 = fmaf(x3.y, w1.y, a31);
            }
            if (t + 1 < T) {
                float* Wd = Wt + (buf^1)*2080;
                #pragma unroll
                for (int s = 0; s < 8; s++) Wd[kk_st*130 + mm0 + 16*s] = r[s];
                if (t + 2 < T) {
                    #pragma unroll
                    for (int s = 0; s < 8; s++) r[s] = Wsrc[(size_t)(mm0 + 16*s)*K + (t+2)*16];
                }
            }
            __syncthreads();
            buf ^= 1;
        }
        int m = m0 + mloc;
        if (m < M) {
            float b0 = bias[m], b1 = bias[m+1];
            int r0 = rg*4;
            float v;
            v = a00 + b0; if (act) v = gelu_f(v); smOut[(r0+0)*opitch + m]   = v;
            v = a01 + b1; if (act) v = gelu_f(v); smOut[(r0+0)*opitch + m+1] = v;
            v = a10 + b0; if (act) v = gelu_f(v); smOut[(r0+1)*opitch + m]   = v;
            v = a11 + b1; if (act) v = gelu_f(v); smOut[(r0+1)*opitch + m+1] = v;
            v = a20 + b0; if (act) v = gelu_f(v); smOut[(r0+2)*opitch + m]   = v;
            v = a21 + b1; if (act) v = gelu_f(v); smOut[(r0+2)*opitch + m+1] = v;
            v = a30 + b0; if (act) v = gelu_f(v); smOut[(r0+3)*opitch + m]   = v;
            v = a31 + b1; if (act) v = gelu_f(v); smOut[(r0+3)*opitch + m+1] = v;
        }
    }
}

__global__ void __launch_bounds__(NT, 3) fused_kernel(
    const float* __restrict__ x_enc, const float* __restrict__ eps,
    const float* __restrict__ p_aw, const float* __restrict__ p_ab,
    const float* __restrict__ b_sc,
    const float* __restrict__ W_r1, const float* __restrict__ b_r1,
    const float* __restrict__ W_r2, const float* __restrict__ b_r2,
    const float* __restrict__ b_r3,
    const float* __restrict__ flow_w, const float* __restrict__ flow_b,
    float* __restrict__ out)
{
    extern __shared__ float smn[];
    float* sA    = smn + P_XN;
    float* sINP  = smn + P_INP;
    float* sB    = smn + P_B;
    float* sPB   = smn + P_PB;
    float* sWT   = smn + P_WT;
    float* sMean = smn + P_MEAN;
    float* sStd  = smn + P_STD;
    float* sScale= smn + P_SCALE;

    int tid = threadIdx.x;
    int n0 = blockIdx.x * ROWS;
    float aw = p_aw[0], ab = p_ab[0];
    int warp = tid >> 5, lane = tid & 31;

    // ---- 1. load x (x_enc[b][l][c] -> xn_raw[r][l], n = b*7+c) ----
    for (int t = tid; t < ROWS*L; t += NT) {
        int r = t & 15, l = t >> 4;
        int n = n0 + r;
        int b = n / 7, c = n - b*7;
        sA[r*L + l] = x_enc[(b*L + l)*7 + c];
    }
    __syncthreads();

    // ---- 2. per-row mean/std (warp w handles rows 2w, 2w+1) ----
    #pragma unroll
    for (int rr = 0; rr < 2; rr++) {
        int r = warp*2 + rr;
        const float* row = sA + r*L;
        float s = 0.f, sq = 0.f;
        for (int l2 = lane; l2 < L; l2 += 32) { float v = row[l2]; s += v; sq += v*v; }
        #pragma unroll
        for (int o = 16; o > 0; o >>= 1) {
            s  += __shfl_xor_sync(0xffffffffu, s, o);
            sq += __shfl_xor_sync(0xffffffffu, sq, o);
        }
        if (lane == 0) {
            float mean = s * (1.f/336.f);
            float var = sq * (1.f/336.f) - mean*mean;
            float sd = sqrtf(var + 1e-5f);
            sMean[r] = mean; sStd[r] = sd; sScale[r] = aw / sd;
        }
    }
    __syncthreads();

    // ---- 3. normalize in place ----
    for (int t = tid; t < ROWS*L; t += NT) {
        int r = t / L;
        sA[t] = (sA[t] - sMean[r]) * sScale[r] + ab;
    }
    __syncthreads();

    // ---- 4. pbar[r][j] = mean over 41 patches of xn[r][8p+j] ----
    {
        int r = tid >> 4, j = tid & 15;
        float s = 0.f;
        #pragma unroll
        for (int pp = 0; pp < 41; pp++) s += sA[r*L + pp*8 + j];
        sPB[r*16 + j] = s * (1.f/41.f);
    }
    // (no sync needed: gemm_tile's internal barriers order pbar writes before any read)

    // ---- 5. shortcut = xn @ Wsc^T + b_sc  -> gmem scratch ----
    gemm_tile(sA, L, L, g_Wsc, b_sc, 96, g_short + (size_t)n0*96, 96, 0, sWT);
    // ---- 6. h = pbar @ Wc^T + bc  -> inp[:,64:192] ----
    gemm_tile(sPB, 16, 16, g_Wc, g_bc, 128, sINP + 64, 192, 0, sWT);
    // ---- 7. [mu|lv] = h @ Wml^T + bml ----
    gemm_tile(sINP + 64, 192, 128, g_Wml, g_bml, 128, sB, 128, 0, sWT);
    __syncthreads();

    // ---- 8+9. reparam (FP64) + planar flows (FP64 scalar chain).
    // Warp per row: rows warp and warp+8. Lane handles dims lane and 32+lane.
    #pragma unroll
    for (int rr = 0; rr < 2; rr++) {
        int r = warp + rr*8;
        int n = n0 + r;
        float mu0 = sB[r*128 + lane];
        float mu1 = sB[r*128 + 32 + lane];
        float lv0 = sB[r*128 + 64 + lane];
        float lv1 = sB[r*128 + 96 + lane];
        out[OFF_MU + n*64 + lane]      = mu0;
        out[OFF_MU + n*64 + 32 + lane] = mu1;
        out[OFF_LV + n*64 + lane]      = lv0;
        out[OFF_LV + n*64 + 32 + lane] = lv1;
        double z0 = (double)mu0 + (double)eps[n*64 + lane]      * exp(0.5 * (double)lv0);
        double z1 = (double)mu1 + (double)eps[n*64 + 32 + lane] * exp(0.5 * (double)lv1);
        double ld = 0.0;
        #pragma unroll
        for (int i = 0; i < 8; i++) {
            double w0 = (double)flow_w[i*64 + lane];
            double w1 = (double)flow_w[i*64 + 32 + lane];
            double dot = z0*w0 + z1*w1;
            #pragma unroll
            for (int o = 16; o > 0; o >>= 1) dot += __shfl_xor_sync(0xffffffffu, dot, o);
            double th = tanh(dot + (double)flow_b[i]);
            z0 += th * g_uhat[i*64 + lane];
            z1 += th * g_uhat[i*64 + 32 + lane];
            ld += log(fabs(1.0 + (1.0 - th*th) * g_cflow[i]) + 1e-6);
        }
        sINP[r*192 + lane]      = (float)z0;
        sINP[r*192 + 32 + lane] = (float)z1;
        if (lane == 0) out[OFF_LD + n] = (float)ld;
    }
    // (flows write sINP; gemm internal barriers order before compute)

    // ---- 10-12. decoder ----
    gemm_tile(sINP, 192, 192, W_r1, b_r1, 256, sB, 256, 1, sWT);   // r1 (gelu)
    gemm_tile(sB, 256, 256, W_r2, b_r2, 512, sA, 512, 1, sWT);     // r2 (gelu), overlaps dead xn/inp
    gemm_tile(sA, 512, 512, g_Wr3, b_r3, 96, sB, 96, 0, sWT);      // recon (overlaps dead r1)
    __syncthreads();

    // ---- 13. denorm + scatter out[b][p][c] ----
    float inv_aw = 1.f / (aw + 1e-10f);
    for (int t = tid; t < ROWS*96; t += NT) {
        int r = t & 15, pcol = t >> 4;
        int n = n0 + r;
        float v = sB[r*96 + pcol] + g_short[(size_t)n*96 + pcol];
        float den = fmaf((v - ab) * inv_aw, sStd[r], sMean[r]);
        int b = n/7, c = n - b*7;
        out[(b*96 + pcol)*7 + c] = den;
    }
}

extern "C" void kernel_launch(void* const* d_in, const int* in_sizes, int n_in,
                              void* d_out, int out_size) {
    const float* x_enc  = (const float*)d_in[0];
    const float* eps    = (const float*)d_in[1];
    const float* aw     = (const float*)d_in[2];
    const float* ab     = (const float*)d_in[3];
    const float* W_sc   = (const float*)d_in[4];
    const float* b_sc   = (const float*)d_in[5];
    const float* W_ts   = (const float*)d_in[6];
    const float* b_ts   = (const float*)d_in[7];
    const float* W_fu   = (const float*)d_in[8];
    const float* b_fu   = (const float*)d_in[9];
    const float* W_mu   = (const float*)d_in[10];
    const float* b_mu   = (const float*)d_in[11];
    const float* W_lv   = (const float*)d_in[12];
    const float* b_lv   = (const float*)d_in[13];
    const float* flow_u = (const float*)d_in[14];
    const float* flow_w = (const float*)d_in[15];
    const float* flow_b = (const float*)d_in[16];
    const float* W_r1   = (const float*)d_in[17];
    const float* b_r1   = (const float*)d_in[18];
    const float* W_r2   = (const float*)d_in[19];
    const float* b_r2   = (const float*)d_in[20];
    const float* W_r3   = (const float*)d_in[21];
    const float* b_r3   = (const float*)d_in[22];
    float* out = (float*)d_out;

    cudaFuncSetAttribute(fused_kernel, cudaFuncAttributeMaxDynamicSharedMemorySize, SMEM_BYTES);

    prep_kernel<<<128, 256>>>(W_sc, W_mu, b_mu, W_lv, b_lv, W_r3,
                              W_fu, b_fu, W_ts, b_ts, flow_u, flow_w);
    fused_kernel<<<448, NT, SMEM_BYTES>>>(x_enc, eps, aw, ab, b_sc,
                                          W_r1, b_r1, W_r2, b_r2, b_r3,
                                          flow_w, flow_b, out);
}